// round 2
// baseline (speedup 1.0000x reference)
#include <cuda_runtime.h>
#include <cstddef>
#include <cstdint>

#define ALPHA  0.2f
#define LOG2E  1.4426950408889634f

// Problem dims (fixed by the reference)
#define NN 8
#define HH 64
#define WD 64
#define TT 8
#define VV 32
#define OO 16

// Precomputed small tensors (prologue kernel -> main kernel)
__device__ float g_adjn[VV * VV];   // normalized adjacency [v][u]
__device__ float g_wa1[TT];         // (W @ a1) * log2(e)
__device__ float g_wa2[TT];         // (W @ a2) * log2(e)

// ---------------- helpers ----------------
__device__ __forceinline__ float ex2f(float x) {
    float y; asm("ex2.approx.f32 %0, %1;" : "=f"(y) : "f"(x)); return y;
}
__device__ __forceinline__ float rcpf(float x) {
    float y; asm("rcp.approx.f32 %0, %1;" : "=f"(y) : "f"(x)); return y;
}
__device__ __forceinline__ float2 ffma2(float2 a, float2 b, float2 c) {
    unsigned long long A, B, C, D;
    A = *reinterpret_cast<unsigned long long*>(&a);
    B = *reinterpret_cast<unsigned long long*>(&b);
    C = *reinterpret_cast<unsigned long long*>(&c);
    asm("fma.rn.f32x2 %0, %1, %2, %3;" : "=l"(D) : "l"(A), "l"(B), "l"(C));
    return *reinterpret_cast<float2*>(&D);
}

// ---------------- prologue: adj_norm + W@a ----------------
__global__ void prep_kernel(const float* __restrict__ W,
                            const float* __restrict__ a,
                            const float* __restrict__ Bp) {
    __shared__ float s_adj[VV * VV];
    __shared__ float smn[32], smx[32];
    __shared__ float s_dis[VV];
    const int tid = threadIdx.x;          // 1024 threads
    const int i = tid >> 5, j = tid & 31; // i = row (also warp id), j = col (lane)

    float v = Bp[tid] + (i == j ? 1.0f : 0.0f);

    // global min/max over all 1024 elements
    float mn = v, mx = v;
    #pragma unroll
    for (int o = 16; o; o >>= 1) {
        mn = fminf(mn, __shfl_xor_sync(0xFFFFFFFFu, mn, o));
        mx = fmaxf(mx, __shfl_xor_sync(0xFFFFFFFFu, mx, o));
    }
    if (j == 0) { smn[i] = mn; smx[i] = mx; }
    __syncthreads();
    if (tid < 32) {
        float m1 = smn[tid], m2 = smx[tid];
        #pragma unroll
        for (int o = 16; o; o >>= 1) {
            m1 = fminf(m1, __shfl_xor_sync(0xFFFFFFFFu, m1, o));
            m2 = fmaxf(m2, __shfl_xor_sync(0xFFFFFFFFu, m2, o));
        }
        if (tid == 0) { smn[0] = m1; smx[0] = m2; }
    }
    __syncthreads();
    mn = smn[0]; mx = smx[0];

    float a0 = (v - mn) / (mx - mn);
    s_adj[tid] = a0;
    __syncthreads();

    if (tid < VV) {
        float s = 0.0f;
        #pragma unroll
        for (int jj = 0; jj < VV; jj++) s += s_adj[tid * VV + jj];
        s_dis[tid] = 1.0f / sqrtf(s);
    }
    __syncthreads();

    g_adjn[tid] = s_dis[i] * a0 * s_dis[j];

    if (tid < TT) {
        float w1 = 0.0f, w2 = 0.0f;
        #pragma unroll
        for (int o = 0; o < OO; o++) {
            float wv = W[tid * OO + o];
            w1 += wv * a[o];
            w2 += wv * a[OO + o];
        }
        g_wa1[tid] = w1 * LOG2E;
        g_wa2[tid] = w2 * LOG2E;
    }
}

// ---------------- main fused kernel ----------------
#define E_STRIDE  66   // padded row stride for e1/e2 (float2-aligned, conflict-benign)
#define AS_STRIDE 65   // padded row stride for att_sum (conflict-free scalar access)

struct Smem {
    float  h[WD * TT * VV];       // 65536 B  [w][t][v], later overwritten by h*g
    float  e1[VV * E_STRIDE];     //  8448 B  [i][w] (log2-domain)
    float  e2[VV * E_STRIDE];     //  8448 B  [j][w]
    float  asum[VV * AS_STRIDE];  //  8320 B  [i][w]
    float  adjn[VV * VV];         //  4096 B  [v][u]
    float2 Wt2[4 * OO];           //   512 B  (W[2tp][o], W[2tp+1][o])
    float  wa1[TT], wa2[TT];      //    64 B
};                                 // total 95,424 B; 2 CTAs/SM fits 228 KB

__global__ __launch_bounds__(256, 2)
void gat_main_kernel(const float* __restrict__ hin,
                     const float* __restrict__ W,
                     float* __restrict__ out) {
    extern __shared__ char smem_raw[];
    Smem& S = *reinterpret_cast<Smem*>(smem_raw);
    const int tid  = threadIdx.x;
    const int lane = tid & 31;
    const int warp = tid >> 5;
    const int n  = blockIdx.x >> 6;
    const int hh = blockIdx.x & 63;

    // ---- stage: load h slice, adjn, W-derived constants ----
    {
        const float4* src = reinterpret_cast<const float4*>(
            hin + (size_t)(n * HH + hh) * (WD * TT * VV));
        float4* dst = reinterpret_cast<float4*>(S.h);
        #pragma unroll
        for (int k = 0; k < 16; k++) dst[tid + k * 256] = src[tid + k * 256];
    }
    for (int k = tid; k < VV * VV; k += 256) S.adjn[k] = g_adjn[k];
    if (tid < 64) {
        int tp = tid >> 4, o = tid & 15;
        S.Wt2[tp * OO + o] = make_float2(W[(2 * tp) * OO + o], W[(2 * tp + 1) * OO + o]);
    }
    if (tid < TT) { S.wa1[tid] = g_wa1[tid]; S.wa2[tid] = g_wa2[tid]; }
    __syncthreads();

    // ---- phase 1: e1[v][w], e2[v][w] (already scaled by log2e via wa) ----
    {
        const int v = tid & 31;
        #pragma unroll
        for (int k = 0; k < 8; k++) {
            const int w = (tid >> 5) + k * 8;
            float s1 = 0.0f, s2 = 0.0f;
            #pragma unroll
            for (int t = 0; t < TT; t++) {
                float hv = S.h[(w * TT + t) * VV + v];
                s1 = fmaf(hv, S.wa1[t], s1);
                s2 = fmaf(hv, S.wa2[t], s2);
            }
            S.e1[v * E_STRIDE + w] = s1;
            S.e2[v * E_STRIDE + w] = s2;
        }
    }
    __syncthreads();

    // ---- phase 2: att_sum[i][w] = sum_j softmax_w(leaky(e1_i + e2_j)) ----
    // warp handles 4 i-rows; lanes hold w = 2*lane, 2*lane+1.
    // No max-subtraction: logits in log2 domain are |x| < ~16, safe in fp32.
    // leaky(c*x) = c*leaky(x) for c>0, so leaky commutes with the log2e scaling.
    {
        const int i0 = warp * 4;
        float2 E1[4], acc[4];
        #pragma unroll
        for (int k = 0; k < 4; k++) {
            E1[k]  = *reinterpret_cast<const float2*>(&S.e1[(i0 + k) * E_STRIDE + 2 * lane]);
            acc[k] = make_float2(0.0f, 0.0f);
        }
        for (int j = 0; j < VV; j++) {
            float2 e2 = *reinterpret_cast<const float2*>(&S.e2[j * E_STRIDE + 2 * lane]);
            #pragma unroll
            for (int k = 0; k < 4; k++) {
                float xa = E1[k].x + e2.x;
                float xb = E1[k].y + e2.y;
                xa = fmaxf(xa, ALPHA * xa);       // leaky (alpha<1)
                xb = fmaxf(xb, ALPHA * xb);
                float pa = ex2f(xa);
                float pb = ex2f(xb);
                float s = pa + pb;
                #pragma unroll
                for (int o = 16; o; o >>= 1) s += __shfl_xor_sync(0xFFFFFFFFu, s, o);
                float r = rcpf(s);
                acc[k].x = fmaf(pa, r, acc[k].x);
                acc[k].y = fmaf(pb, r, acc[k].y);
            }
        }
        #pragma unroll
        for (int k = 0; k < 4; k++) {
            S.asum[(i0 + k) * AS_STRIDE + 2 * lane]     = acc[k].x;
            S.asum[(i0 + k) * AS_STRIDE + 2 * lane + 1] = acc[k].y;
        }
    }
    __syncthreads();

    // ---- phase hg: in-place h[w][t][v] *= att_sum[v][w] ----
    {
        const int v = tid & 31;
        const int t = tid >> 5;
        #pragma unroll 8
        for (int k = 0; k < 64; k++) {          // k == w
            float g = S.asum[v * AS_STRIDE + k];
            S.h[(k * TT + t) * VV + v] *= g;
        }
    }
    __syncthreads();

    // ---- phase 3: out[o][u] = elu( sum_t W[t][o] * (sum_v hg[w][t][v]*adjn[v][u]) ) ----
    // warp handles w = warp + 8k; lanes = u. Packed f32x2 over v-pairs / t-pairs.
    {
        const int u = lane;
        float2 adj2[16];
        #pragma unroll
        for (int vp = 0; vp < 16; vp++)
            adj2[vp] = make_float2(S.adjn[(2 * vp) * VV + u],
                                   S.adjn[(2 * vp + 1) * VV + u]);

        #pragma unroll 1
        for (int k = 0; k < 8; k++) {
            const int w = warp + k * 8;
            const float* hg = &S.h[w * TT * VV];

            float2 acc2[TT];
            #pragma unroll
            for (int t = 0; t < TT; t++) acc2[t] = make_float2(0.0f, 0.0f);

            #pragma unroll
            for (int vp = 0; vp < 16; vp++) {
                #pragma unroll
                for (int t = 0; t < TT; t++) {
                    float2 h2 = *reinterpret_cast<const float2*>(&hg[t * VV + 2 * vp]);
                    acc2[t] = ffma2(h2, adj2[vp], acc2[t]);
                }
            }
            float2 Pt2[4];
            #pragma unroll
            for (int tp = 0; tp < 4; tp++)
                Pt2[tp] = make_float2(acc2[2 * tp].x + acc2[2 * tp].y,
                                      acc2[2 * tp + 1].x + acc2[2 * tp + 1].y);

            float* outp = out + ((size_t)((n * WD + w) * HH + hh)) * (OO * VV) + u;
            #pragma unroll
            for (int o = 0; o < OO; o++) {
                float2 s2 = make_float2(0.0f, 0.0f);
                #pragma unroll
                for (int tp = 0; tp < 4; tp++)
                    s2 = ffma2(Pt2[tp], S.Wt2[tp * OO + o], s2);
                float s = s2.x + s2.y;
                // ELU: exact-ish for tiny negatives (3-term expm1), ex2 otherwise
                float r;
                if (s >= 0.0f) {
                    r = s;
                } else if (s > -0.0625f) {
                    r = s * fmaf(s, fmaf(s, 0.166666667f, 0.5f), 1.0f);
                } else {
                    r = ex2f(s * LOG2E) - 1.0f;
                }
                outp[o * VV] = r;
            }
        }
    }
}

// ---------------- launch ----------------
extern "C" void kernel_launch(void* const* d_in, const int* in_sizes, int n_in,
                              void* d_out, int out_size) {
    const float *h = nullptr, *W = nullptr, *a = nullptr, *Bp = nullptr;
    for (int i = 0; i < n_in; i++) {
        switch (in_sizes[i]) {
            case NN * HH * WD * TT * VV: h  = (const float*)d_in[i]; break; // 8388608
            case TT * OO:                W  = (const float*)d_in[i]; break; // 128
            case 2 * OO:                 a  = (const float*)d_in[i]; break; // 32
            case VV * VV:                Bp = (const float*)d_in[i]; break; // 1024
            default: break;
        }
    }
    float* out = (float*)d_out;

    cudaFuncSetAttribute(gat_main_kernel,
                         cudaFuncAttributeMaxDynamicSharedMemorySize,
                         (int)sizeof(Smem));

    prep_kernel<<<1, 1024>>>(W, a, Bp);
    gat_main_kernel<<<NN * HH, 256, sizeof(Smem)>>>(h, W, out);
}

// round 4
// speedup vs baseline: 1.0045x; 1.0045x over previous
#include <cuda_runtime.h>
#include <cstddef>
#include <cstdint>

#define ALPHA  0.2f
#define LOG2E  1.4426950408889634f

// Problem dims (fixed by the reference)
#define NN 8
#define HH 64
#define WD 64
#define TT 8
#define VV 32
#define OO 16

__device__ float g_adjn[VV * VV];   // normalized adjacency [v][u]
__device__ float g_wa1[TT];         // (W @ a1) * log2(e)
__device__ float g_wa2[TT];         // (W @ a2) * log2(e)

// ---------------- helpers ----------------
__device__ __forceinline__ float ex2f(float x) {
    float y; asm("ex2.approx.f32 %0, %1;" : "=f"(y) : "f"(x)); return y;
}
__device__ __forceinline__ float rcpf(float x) {
    float y; asm("rcp.approx.f32 %0, %1;" : "=f"(y) : "f"(x)); return y;
}
__device__ __forceinline__ float2 ffma2(float2 a, float2 b, float2 c) {
    unsigned long long A, B, C, D;
    A = *reinterpret_cast<unsigned long long*>(&a);
    B = *reinterpret_cast<unsigned long long*>(&b);
    C = *reinterpret_cast<unsigned long long*>(&c);
    asm("fma.rn.f32x2 %0, %1, %2, %3;" : "=l"(D) : "l"(A), "l"(B), "l"(C));
    return *reinterpret_cast<float2*>(&D);
}
__device__ __forceinline__ float2 fmul2(float2 a, float2 b) {
    unsigned long long A, B, D;
    A = *reinterpret_cast<unsigned long long*>(&a);
    B = *reinterpret_cast<unsigned long long*>(&b);
    asm("mul.rn.f32x2 %0, %1, %2;" : "=l"(D) : "l"(A), "l"(B));
    return *reinterpret_cast<float2*>(&D);
}

// ---------------- prologue: adj_norm + W@a ----------------
__global__ void prep_kernel(const float* __restrict__ W,
                            const float* __restrict__ a,
                            const float* __restrict__ Bp) {
    __shared__ float s_adj[VV * VV];
    __shared__ float smn[32], smx[32];
    __shared__ float s_dis[VV];
    const int tid = threadIdx.x;          // 1024 threads
    const int i = tid >> 5, j = tid & 31;

    float v = Bp[tid] + (i == j ? 1.0f : 0.0f);

    float mn = v, mx = v;
    #pragma unroll
    for (int o = 16; o; o >>= 1) {
        mn = fminf(mn, __shfl_xor_sync(0xFFFFFFFFu, mn, o));
        mx = fmaxf(mx, __shfl_xor_sync(0xFFFFFFFFu, mx, o));
    }
    if (j == 0) { smn[i] = mn; smx[i] = mx; }
    __syncthreads();
    if (tid < 32) {
        float m1 = smn[tid], m2 = smx[tid];
        #pragma unroll
        for (int o = 16; o; o >>= 1) {
            m1 = fminf(m1, __shfl_xor_sync(0xFFFFFFFFu, m1, o));
            m2 = fmaxf(m2, __shfl_xor_sync(0xFFFFFFFFu, m2, o));
        }
        if (tid == 0) { smn[0] = m1; smx[0] = m2; }
    }
    __syncthreads();
    mn = smn[0]; mx = smx[0];

    float a0 = (v - mn) / (mx - mn);
    s_adj[tid] = a0;
    __syncthreads();

    if (tid < VV) {
        float s = 0.0f;
        #pragma unroll
        for (int jj = 0; jj < VV; jj++) s += s_adj[tid * VV + jj];
        s_dis[tid] = 1.0f / sqrtf(s);
    }
    __syncthreads();

    g_adjn[tid] = s_dis[i] * a0 * s_dis[j];

    if (tid < TT) {
        float w1 = 0.0f, w2 = 0.0f;
        #pragma unroll
        for (int o = 0; o < OO; o++) {
            float wv = W[tid * OO + o];
            w1 += wv * a[o];
            w2 += wv * a[OO + o];
        }
        g_wa1[tid] = w1 * LOG2E;
        g_wa2[tid] = w2 * LOG2E;
    }
}

// ---------------- main fused kernel ----------------
// exp factorization:  exp(leaky(x1+x2)) = max(2^x1 * 2^x2, 2^(.2 x1) * 2^(.2 x2))
// (log2 domain; 2^x > 2^(0.2x) iff x > 0, which is exactly the leaky select)

#define E2_STRIDE 66   // floats per E2p/E2n row (even -> float2-aligned pass-B reads)

struct Smem {
    float  h[WD * TT * VV];        // 65536 B  [w][t][v], overwritten by h*g
    float2 E1pk[WD * VV];          // 16384 B  [w][i] = (2^e1, 2^(.2 e1))
    float  E2p[VV * E2_STRIDE];    //  8448 B  [j][w] = 2^e2
    float  E2n[VV * E2_STRIDE];    //  8448 B  [j][w] = 2^(.2 e2)
    float  r[VV * VV];             //  4096 B  [i][j] = 1/denominator
    float  asum[WD * VV];          //  8192 B  [w][i] att_sum (transposed)
    float2 Wt2[4 * OO];            //   512 B  (W[2tp][o], W[2tp+1][o])
    float  wa1[TT], wa2[TT];       //    64 B
};                                  // total 111,680 B -> 2 CTAs/SM (with 1KB/CTA reserve)

__global__ __launch_bounds__(256, 2)
void gat_main_kernel(const float* __restrict__ hin,
                     const float* __restrict__ W,
                     float* __restrict__ out) {
    extern __shared__ char smem_raw[];
    Smem& S = *reinterpret_cast<Smem*>(smem_raw);
    const int tid  = threadIdx.x;
    const int lane = tid & 31;
    const int warp = tid >> 5;
    const int n  = blockIdx.x >> 6;
    const int hh = blockIdx.x & 63;

    // ---- stage ----
    {
        const float4* src = reinterpret_cast<const float4*>(
            hin + (size_t)(n * HH + hh) * (WD * TT * VV));
        float4* dst = reinterpret_cast<float4*>(S.h);
        #pragma unroll
        for (int k = 0; k < 16; k++) dst[tid + k * 256] = src[tid + k * 256];
    }
    if (tid < 64) {
        int tp = tid >> 4, o = tid & 15;
        S.Wt2[tp * OO + o] = make_float2(W[(2 * tp) * OO + o], W[(2 * tp + 1) * OO + o]);
    }
    if (tid < TT) { S.wa1[tid] = g_wa1[tid]; S.wa2[tid] = g_wa2[tid]; }
    __syncthreads();

    // ---- phase 1: logits -> exponential tables (log2 domain) ----
    {
        const int v = lane;                       // v = node index
        #pragma unroll
        for (int k = 0; k < 8; k++) {
            const int w = warp + k * 8;
            float s1 = 0.0f, s2 = 0.0f;
            #pragma unroll
            for (int t = 0; t < TT; t++) {
                float hv = S.h[(w * TT + t) * VV + v];
                s1 = fmaf(hv, S.wa1[t], s1);
                s2 = fmaf(hv, S.wa2[t], s2);
            }
            S.E1pk[w * VV + v] = make_float2(ex2f(s1), ex2f(ALPHA * s1));  // [w][i]
            S.E2p[v * E2_STRIDE + w] = ex2f(s2);                           // [j][w]
            S.E2n[v * E2_STRIDE + w] = ex2f(ALPHA * s2);
        }
    }
    __syncthreads();

    // ---- pass A: r[i][j] = 1 / sum_w max(E1p*E2p, E1n*E2n) ----
    // warp -> 4 i rows, lane = j, serial w accumulation: no shuffles.
    // E1pk reads are warp-uniform (broadcast); E2 reads 2-way conflicted.
    {
        const int i0 = warp * 4;
        const int j  = lane;
        float s0 = 0.f, s1 = 0.f, s2 = 0.f, s3 = 0.f;
        #pragma unroll 4
        for (int w = 0; w < WD; w++) {
            float2 e2 = make_float2(S.E2p[j * E2_STRIDE + w],
                                    S.E2n[j * E2_STRIDE + w]);
            float2 p0 = fmul2(S.E1pk[w * VV + i0 + 0], e2);
            float2 p1 = fmul2(S.E1pk[w * VV + i0 + 1], e2);
            float2 p2 = fmul2(S.E1pk[w * VV + i0 + 2], e2);
            float2 p3 = fmul2(S.E1pk[w * VV + i0 + 3], e2);
            s0 += fmaxf(p0.x, p0.y);
            s1 += fmaxf(p1.x, p1.y);
            s2 += fmaxf(p2.x, p2.y);
            s3 += fmaxf(p3.x, p3.y);
        }
        S.r[(i0 + 0) * VV + j] = rcpf(s0);
        S.r[(i0 + 1) * VV + j] = rcpf(s1);
        S.r[(i0 + 2) * VV + j] = rcpf(s2);
        S.r[(i0 + 3) * VV + j] = rcpf(s3);
    }
    __syncthreads();

    // ---- pass B: asum[w][i] = sum_j max(E1p*E2p, E1n*E2n) * r[i][j] ----
    // warp -> 4 i rows, lane = w-pair, serial j loop: no shuffles.
    {
        const int i0 = warp * 4;
        const int w0 = 2 * lane;
        float2 E1p2[4], E1n2[4];
        #pragma unroll
        for (int k = 0; k < 4; k++) {
            float2 ea = S.E1pk[w0 * VV + i0 + k];        // one-time conflicted loads
            float2 eb = S.E1pk[(w0 + 1) * VV + i0 + k];
            E1p2[k] = make_float2(ea.x, eb.x);
            E1n2[k] = make_float2(ea.y, eb.y);
        }
        float2 acc[4];
        #pragma unroll
        for (int k = 0; k < 4; k++) acc[k] = make_float2(0.f, 0.f);

        #pragma unroll 4
        for (int j = 0; j < VV; j++) {
            float2 p2 = *reinterpret_cast<const float2*>(&S.E2p[j * E2_STRIDE + w0]);
            float2 n2 = *reinterpret_cast<const float2*>(&S.E2n[j * E2_STRIDE + w0]);
            #pragma unroll
            for (int k = 0; k < 4; k++) {
                float rr = S.r[(i0 + k) * VV + j];       // broadcast
                float2 pp = fmul2(E1p2[k], p2);
                float2 pn = fmul2(E1n2[k], n2);
                acc[k].x = fmaf(fmaxf(pp.x, pn.x), rr, acc[k].x);
                acc[k].y = fmaf(fmaxf(pp.y, pn.y), rr, acc[k].y);
            }
        }
        #pragma unroll
        for (int k = 0; k < 4; k++) {
            S.asum[w0 * VV + i0 + k]       = acc[k].x;   // one-time conflicted stores
            S.asum[(w0 + 1) * VV + i0 + k] = acc[k].y;
        }
    }
    __syncthreads();

    // ---- phase hg: in-place h[w][t][v] *= asum[w][v] ----
    {
        const int v = lane;
        const int t = warp;
        #pragma unroll 8
        for (int k = 0; k < 64; k++) {                   // k == w
            float g = S.asum[k * VV + v];                // consecutive, conflict-free
            S.h[(k * TT + t) * VV + v] *= g;
        }
    }
    __syncthreads();

    // ---- phase 3: out[o][u] = elu( sum_t W[t][o] * sum_v hg[w][t][v]*adjn[v][u] ) ----
    {
        const int u = lane;
        float2 adj2[16];
        #pragma unroll
        for (int vp = 0; vp < 16; vp++)
            adj2[vp] = make_float2(g_adjn[(2 * vp) * VV + u],    // coalesced, L1/L2-hot
                                   g_adjn[(2 * vp + 1) * VV + u]);

        #pragma unroll 1
        for (int k = 0; k < 8; k++) {
            const int w = warp + k * 8;
            const float* hg = &S.h[w * TT * VV];

            float2 acc2[TT];
            #pragma unroll
            for (int t = 0; t < TT; t++) acc2[t] = make_float2(0.0f, 0.0f);

            #pragma unroll
            for (int vq = 0; vq < 8; vq++) {
                #pragma unroll
                for (int t = 0; t < TT; t++) {
                    float4 h4 = *reinterpret_cast<const float4*>(&hg[t * VV + 4 * vq]); // broadcast
                    acc2[t] = ffma2(make_float2(h4.x, h4.y), adj2[2 * vq],     acc2[t]);
                    acc2[t] = ffma2(make_float2(h4.z, h4.w), adj2[2 * vq + 1], acc2[t]);
                }
            }
            float2 Pt2[4];
            #pragma unroll
            for (int tp = 0; tp < 4; tp++)
                Pt2[tp] = make_float2(acc2[2 * tp].x + acc2[2 * tp].y,
                                      acc2[2 * tp + 1].x + acc2[2 * tp + 1].y);

            float* outp = out + ((size_t)((n * WD + w) * HH + hh)) * (OO * VV) + u;
            #pragma unroll
            for (int o = 0; o < OO; o++) {
                float2 s2 = make_float2(0.0f, 0.0f);
                #pragma unroll
                for (int tp = 0; tp < 4; tp++)
                    s2 = ffma2(Pt2[tp], S.Wt2[tp * OO + o], s2);
                float s = s2.x + s2.y;
                float r;
                if (s >= 0.0f) {
                    r = s;
                } else if (s > -0.0625f) {
                    r = s * fmaf(s, fmaf(s, 0.166666667f, 0.5f), 1.0f);
                } else {
                    r = ex2f(s * LOG2E) - 1.0f;
                }
                outp[o * VV] = r;
            }
        }
    }
}

// ---------------- launch ----------------
extern "C" void kernel_launch(void* const* d_in, const int* in_sizes, int n_in,
                              void* d_out, int out_size) {
    const float *h = nullptr, *W = nullptr, *a = nullptr, *Bp = nullptr;
    for (int i = 0; i < n_in; i++) {
        switch (in_sizes[i]) {
            case NN * HH * WD * TT * VV: h  = (const float*)d_in[i]; break; // 8388608
            case TT * OO:                W  = (const float*)d_in[i]; break; // 128
            case 2 * OO:                 a  = (const float*)d_in[i]; break; // 32
            case VV * VV:                Bp = (const float*)d_in[i]; break; // 1024
            default: break;
        }
    }
    float* out = (float*)d_out;

    cudaFuncSetAttribute(gat_main_kernel,
                         cudaFuncAttributeMaxDynamicSharedMemorySize,
                         (int)sizeof(Smem));

    prep_kernel<<<1, 1024>>>(W, a, Bp);
    gat_main_kernel<<<NN * HH, 256, sizeof(Smem)>>>(h, W, out);
}

// round 6
// speedup vs baseline: 1.1497x; 1.1446x over previous
#include <cuda_runtime.h>
#include <cstddef>
#include <cstdint>

#define ALPHA  0.2f
#define LOG2E  1.4426950408889634f

// Problem dims (fixed by the reference)
#define NN 8
#define HH 64
#define WD 64
#define TT 8
#define VV 32
#define OO 16

__device__ float g_adjn[VV * VV];   // normalized adjacency [v][u]
__device__ float g_wa1[TT];         // (W @ a1) * log2(e)
__device__ float g_wa2[TT];         // (W @ a2) * log2(e)

// ---------------- helpers ----------------
__device__ __forceinline__ float ex2f(float x) {
    float y; asm("ex2.approx.f32 %0, %1;" : "=f"(y) : "f"(x)); return y;
}
__device__ __forceinline__ float rcpf(float x) {
    float y; asm("rcp.approx.f32 %0, %1;" : "=f"(y) : "f"(x)); return y;
}
__device__ __forceinline__ float2 ffma2(float2 a, float2 b, float2 c) {
    unsigned long long A, B, C, D;
    A = *reinterpret_cast<unsigned long long*>(&a);
    B = *reinterpret_cast<unsigned long long*>(&b);
    C = *reinterpret_cast<unsigned long long*>(&c);
    asm("fma.rn.f32x2 %0, %1, %2, %3;" : "=l"(D) : "l"(A), "l"(B), "l"(C));
    return *reinterpret_cast<float2*>(&D);
}
__device__ __forceinline__ float2 fmul2(float2 a, float2 b) {
    unsigned long long A, B, D;
    A = *reinterpret_cast<unsigned long long*>(&a);
    B = *reinterpret_cast<unsigned long long*>(&b);
    asm("mul.rn.f32x2 %0, %1, %2;" : "=l"(D) : "l"(A), "l"(B));
    return *reinterpret_cast<float2*>(&D);
}

// ---------------- prologue: adj_norm + W@a ----------------
__global__ void prep_kernel(const float* __restrict__ W,
                            const float* __restrict__ a,
                            const float* __restrict__ Bp) {
    __shared__ float s_adj[VV * VV];
    __shared__ float smn[32], smx[32];
    __shared__ float s_dis[VV];
    const int tid = threadIdx.x;          // 1024 threads
    const int i = tid >> 5, j = tid & 31;

    float v = Bp[tid] + (i == j ? 1.0f : 0.0f);

    float mn = v, mx = v;
    #pragma unroll
    for (int o = 16; o; o >>= 1) {
        mn = fminf(mn, __shfl_xor_sync(0xFFFFFFFFu, mn, o));
        mx = fmaxf(mx, __shfl_xor_sync(0xFFFFFFFFu, mx, o));
    }
    if (j == 0) { smn[i] = mn; smx[i] = mx; }
    __syncthreads();
    if (tid < 32) {
        float m1 = smn[tid], m2 = smx[tid];
        #pragma unroll
        for (int o = 16; o; o >>= 1) {
            m1 = fminf(m1, __shfl_xor_sync(0xFFFFFFFFu, m1, o));
            m2 = fmaxf(m2, __shfl_xor_sync(0xFFFFFFFFu, m2, o));
        }
        if (tid == 0) { smn[0] = m1; smx[0] = m2; }
    }
    __syncthreads();
    mn = smn[0]; mx = smx[0];

    float a0 = (v - mn) / (mx - mn);
    s_adj[tid] = a0;
    __syncthreads();

    if (tid < VV) {
        float s = 0.0f;
        #pragma unroll
        for (int jj = 0; jj < VV; jj++) s += s_adj[tid * VV + jj];
        s_dis[tid] = 1.0f / sqrtf(s);
    }
    __syncthreads();

    g_adjn[tid] = s_dis[i] * a0 * s_dis[j];

    if (tid < TT) {
        float w1 = 0.0f, w2 = 0.0f;
        #pragma unroll
        for (int o = 0; o < OO; o++) {
            float wv = W[tid * OO + o];
            w1 += wv * a[o];
            w2 += wv * a[OO + o];
        }
        g_wa1[tid] = w1 * LOG2E;
        g_wa2[tid] = w2 * LOG2E;
    }
}

// ---------------- main fused kernel ----------------
// exp factorization:  exp(leaky(x1+x2)) = max(2^x1 * 2^x2, 2^(.2 x1) * 2^(.2 x2))
// (log2 domain; 2^x > 2^(0.2x) iff x > 0, which is exactly the leaky select)

#define E2_STRIDE 66   // floats per E2p/E2n row

struct Smem {
    union {
        struct {                           // live: phases 1..B
            float2 E1pk[WD * VV];          // 16384 B  [w][i] = (2^e1, 2^(.2 e1))
            float  E2p[VV * E2_STRIDE];    //  8448 B  [j][w] = 2^e2
            float  E2n[VV * E2_STRIDE];    //  8448 B  [j][w] = 2^(.2 e2)
        } e;
        struct {                           // live: phase 3 (after sync)
            float  hg[8 * TT * VV];        //  8192 B  staged h*g chunk [wl][t][v]
            float  adjn[VV * VV];          //  4096 B  [v][u]
        } p3;
    } u;                                   // 33280 B
    float  r[VV * VV];                     //  4096 B  [i][j] = 1/denominator
    float  asum[WD * VV];                  //  8192 B  [w][v] att_sum
    float2 Wt2[4 * OO];                    //   512 B  (W[2tp][o], W[2tp+1][o])
    float  wa1[TT], wa2[TT];               //    64 B
};                                          // total 46,144 B -> 4 CTAs/SM, single wave

__global__ __launch_bounds__(256, 4)
void gat_main_kernel(const float* __restrict__ hin,
                     const float* __restrict__ W,
                     float* __restrict__ out) {
    extern __shared__ char smem_raw[];
    Smem& S = *reinterpret_cast<Smem*>(smem_raw);
    const int tid  = threadIdx.x;
    const int lane = tid & 31;
    const int warp = tid >> 5;
    const int n  = blockIdx.x >> 6;
    const int hh = blockIdx.x & 63;
    const float* __restrict__ hbase = hin + (size_t)(n * HH + hh) * (WD * TT * VV);

    // ---- stage constants ----
    if (tid < 64) {
        int tp = tid >> 4, o = tid & 15;
        S.Wt2[tp * OO + o] = make_float2(W[(2 * tp) * OO + o], W[(2 * tp + 1) * OO + o]);
    }
    if (tid < TT) { S.wa1[tid] = g_wa1[tid]; S.wa2[tid] = g_wa2[tid]; }
    __syncthreads();   // wa needed below

    // ---- phase 1: logits -> exponential tables, streaming h from gmem ----
    // slot = (w, vq): 512 slots, thread handles slot tid and tid+256.
    {
        float wa1r[TT], wa2r[TT];
        #pragma unroll
        for (int t = 0; t < TT; t++) { wa1r[t] = S.wa1[t]; wa2r[t] = S.wa2[t]; }
        #pragma unroll
        for (int s = 0; s < 2; s++) {
            const int slot = tid + s * 256;
            const int w  = slot >> 3;
            const int vq = slot & 7;
            float4 s1 = make_float4(0.f, 0.f, 0.f, 0.f);
            float4 s2 = make_float4(0.f, 0.f, 0.f, 0.f);
            #pragma unroll
            for (int t = 0; t < TT; t++) {
                float4 h4 = *reinterpret_cast<const float4*>(
                    &hbase[(w * TT + t) * VV + 4 * vq]);   // coalesced LDG.128
                s1.x = fmaf(h4.x, wa1r[t], s1.x);  s2.x = fmaf(h4.x, wa2r[t], s2.x);
                s1.y = fmaf(h4.y, wa1r[t], s1.y);  s2.y = fmaf(h4.y, wa2r[t], s2.y);
                s1.z = fmaf(h4.z, wa1r[t], s1.z);  s2.z = fmaf(h4.z, wa2r[t], s2.z);
                s1.w = fmaf(h4.w, wa1r[t], s1.w);  s2.w = fmaf(h4.w, wa2r[t], s2.w);
            }
            const float l1[4] = {s1.x, s1.y, s1.z, s1.w};
            const float l2[4] = {s2.x, s2.y, s2.z, s2.w};
            #pragma unroll
            for (int c = 0; c < 4; c++) {
                const int v = 4 * vq + c;
                S.u.e.E1pk[w * VV + v] = make_float2(ex2f(l1[c]), ex2f(ALPHA * l1[c]));
                S.u.e.E2p[v * E2_STRIDE + w] = ex2f(l2[c]);
                S.u.e.E2n[v * E2_STRIDE + w] = ex2f(ALPHA * l2[c]);
            }
        }
    }
    __syncthreads();

    // ---- pass A: r[i][j] = 1 / sum_w max(E1p*E2p, E1n*E2n) ----
    {
        const int i0 = warp * 4;
        const int j  = lane;
        float s0 = 0.f, s1 = 0.f, s2 = 0.f, s3 = 0.f;
        #pragma unroll 4
        for (int w = 0; w < WD; w++) {
            float2 e2 = make_float2(S.u.e.E2p[j * E2_STRIDE + w],
                                    S.u.e.E2n[j * E2_STRIDE + w]);
            float2 p0 = fmul2(S.u.e.E1pk[w * VV + i0 + 0], e2);
            float2 p1 = fmul2(S.u.e.E1pk[w * VV + i0 + 1], e2);
            float2 p2 = fmul2(S.u.e.E1pk[w * VV + i0 + 2], e2);
            float2 p3 = fmul2(S.u.e.E1pk[w * VV + i0 + 3], e2);
            s0 += fmaxf(p0.x, p0.y);
            s1 += fmaxf(p1.x, p1.y);
            s2 += fmaxf(p2.x, p2.y);
            s3 += fmaxf(p3.x, p3.y);
        }
        S.r[(i0 + 0) * VV + j] = rcpf(s0);
        S.r[(i0 + 1) * VV + j] = rcpf(s1);
        S.r[(i0 + 2) * VV + j] = rcpf(s2);
        S.r[(i0 + 3) * VV + j] = rcpf(s3);
    }
    __syncthreads();

    // ---- pass B: asum[w][i] = sum_j max(E1p*E2p, E1n*E2n) * r[i][j] ----
    {
        const int i0 = warp * 4;
        const int w0 = 2 * lane;
        float2 E1p2[4], E1n2[4];
        #pragma unroll
        for (int k = 0; k < 4; k++) {
            float2 ea = S.u.e.E1pk[w0 * VV + i0 + k];
            float2 eb = S.u.e.E1pk[(w0 + 1) * VV + i0 + k];
            E1p2[k] = make_float2(ea.x, eb.x);
            E1n2[k] = make_float2(ea.y, eb.y);
        }
        float2 acc[4];
        #pragma unroll
        for (int k = 0; k < 4; k++) acc[k] = make_float2(0.f, 0.f);

        #pragma unroll 4
        for (int j = 0; j < VV; j++) {
            float2 p2 = *reinterpret_cast<const float2*>(&S.u.e.E2p[j * E2_STRIDE + w0]);
            float2 n2 = *reinterpret_cast<const float2*>(&S.u.e.E2n[j * E2_STRIDE + w0]);
            #pragma unroll
            for (int k = 0; k < 4; k++) {
                float rr = S.r[(i0 + k) * VV + j];
                float2 pp = fmul2(E1p2[k], p2);
                float2 pn = fmul2(E1n2[k], n2);
                acc[k].x = fmaf(fmaxf(pp.x, pn.x), rr, acc[k].x);
                acc[k].y = fmaf(fmaxf(pp.y, pn.y), rr, acc[k].y);
            }
        }
        #pragma unroll
        for (int k = 0; k < 4; k++) {
            S.asum[w0 * VV + i0 + k]       = acc[k].x;
            S.asum[(w0 + 1) * VV + i0 + k] = acc[k].y;
        }
    }
    __syncthreads();   // E-tables dead beyond this point; union region reusable

    // ---- stage adjn into the overlay ----
    reinterpret_cast<float4*>(S.u.p3.adjn)[tid] =
        reinterpret_cast<const float4*>(g_adjn)[tid];   // 256 * 16B = 4 KB
    __syncthreads();

    // ---- phase 3 (chunked over w): stage hg = h*asum, then contract ----
    #pragma unroll 1
    for (int c = 0; c < 8; c++) {
        // stage: 8 w's worth of h*g into smem (h from gmem, L2-hot)
        #pragma unroll
        for (int s = 0; s < 2; s++) {
            const int idx = tid + s * 256;      // 512 float4 slots
            const int q  = idx & 7;
            const int t  = (idx >> 3) & 7;
            const int wl = idx >> 6;            // 0..7
            const int w  = c * 8 + wl;
            float4 h4 = *reinterpret_cast<const float4*>(
                &hbase[(w * TT + t) * VV + 4 * q]);                 // coalesced
            float4 a4 = *reinterpret_cast<const float4*>(
                &S.asum[w * VV + 4 * q]);
            float2 ga = fmul2(make_float2(h4.x, h4.y), make_float2(a4.x, a4.y));
            float2 gb = fmul2(make_float2(h4.z, h4.w), make_float2(a4.z, a4.w));
            *reinterpret_cast<float4*>(&S.u.p3.hg[(wl * TT + t) * VV + 4 * q]) =
                make_float4(ga.x, ga.y, gb.x, gb.y);
        }
        __syncthreads();

        // compute: warp handles w = c*8 + warp; lane = u
        {
            const int u = lane;
            const int w = c * 8 + warp;
            const float* hg = &S.u.p3.hg[warp * TT * VV];

            float2 acc2[TT];
            #pragma unroll
            for (int t = 0; t < TT; t++) acc2[t] = make_float2(0.0f, 0.0f);

            #pragma unroll
            for (int vq = 0; vq < 8; vq++) {
                const float2 adjA = make_float2(S.u.p3.adjn[(4 * vq + 0) * VV + u],
                                                S.u.p3.adjn[(4 * vq + 1) * VV + u]);
                const float2 adjB = make_float2(S.u.p3.adjn[(4 * vq + 2) * VV + u],
                                                S.u.p3.adjn[(4 * vq + 3) * VV + u]);
                #pragma unroll
                for (int t = 0; t < TT; t++) {
                    float4 h4 = *reinterpret_cast<const float4*>(&hg[t * VV + 4 * vq]); // broadcast
                    acc2[t] = ffma2(make_float2(h4.x, h4.y), adjA, acc2[t]);
                    acc2[t] = ffma2(make_float2(h4.z, h4.w), adjB, acc2[t]);
                }
            }
            float2 Pt2[4];
            #pragma unroll
            for (int tp = 0; tp < 4; tp++)
                Pt2[tp] = make_float2(acc2[2 * tp].x + acc2[2 * tp].y,
                                      acc2[2 * tp + 1].x + acc2[2 * tp + 1].y);

            float* outp = out + ((size_t)((n * WD + w) * HH + hh)) * (OO * VV) + u;
            #pragma unroll
            for (int o = 0; o < OO; o++) {
                float2 s2 = make_float2(0.0f, 0.0f);
                #pragma unroll
                for (int tp = 0; tp < 4; tp++)
                    s2 = ffma2(Pt2[tp], S.Wt2[tp * OO + o], s2);
                float s = s2.x + s2.y;
                float r;
                if (s >= 0.0f) {
                    r = s;
                } else if (s > -0.0625f) {
                    r = s * fmaf(s, fmaf(s, 0.166666667f, 0.5f), 1.0f);
                } else {
                    r = ex2f(s * LOG2E) - 1.0f;
                }
                outp[o * VV] = r;
            }
        }
        __syncthreads();   // protect hg before next chunk overwrite
    }
}

// ---------------- launch ----------------
extern "C" void kernel_launch(void* const* d_in, const int* in_sizes, int n_in,
                              void* d_out, int out_size) {
    const float *h = nullptr, *W = nullptr, *a = nullptr, *Bp = nullptr;
    for (int i = 0; i < n_in; i++) {
        switch (in_sizes[i]) {
            case NN * HH * WD * TT * VV: h  = (const float*)d_in[i]; break; // 8388608
            case TT * OO:                W  = (const float*)d_in[i]; break; // 128
            case 2 * OO:                 a  = (const float*)d_in[i]; break; // 32
            case VV * VV:                Bp = (const float*)d_in[i]; break; // 1024
            default: break;
        }
    }
    float* out = (float*)d_out;

    cudaFuncSetAttribute(gat_main_kernel,
                         cudaFuncAttributeMaxDynamicSharedMemorySize,
                         (int)sizeof(Smem));

    prep_kernel<<<1, 1024>>>(W, a, Bp);
    gat_main_kernel<<<NN * HH, 256, sizeof(Smem)>>>(h, W, out);
}

// round 7
// speedup vs baseline: 1.2892x; 1.1213x over previous
#include <cuda_runtime.h>
#include <cstddef>
#include <cstdint>

#define ALPHA  0.2f
#define LOG2E  1.4426950408889634f

// Problem dims (fixed by the reference)
#define NN 8
#define HH 64
#define WD 64
#define TT 8
#define VV 32
#define OO 16

// ---------------- helpers ----------------
__device__ __forceinline__ float ex2f(float x) {
    float y; asm("ex2.approx.f32 %0, %1;" : "=f"(y) : "f"(x)); return y;
}
__device__ __forceinline__ float rcpf(float x) {
    float y; asm("rcp.approx.f32 %0, %1;" : "=f"(y) : "f"(x)); return y;
}
__device__ __forceinline__ float2 ffma2(float2 a, float2 b, float2 c) {
    unsigned long long A, B, C, D;
    A = *reinterpret_cast<unsigned long long*>(&a);
    B = *reinterpret_cast<unsigned long long*>(&b);
    C = *reinterpret_cast<unsigned long long*>(&c);
    asm("fma.rn.f32x2 %0, %1, %2, %3;" : "=l"(D) : "l"(A), "l"(B), "l"(C));
    return *reinterpret_cast<float2*>(&D);
}
__device__ __forceinline__ float2 fmul2(float2 a, float2 b) {
    unsigned long long A, B, D;
    A = *reinterpret_cast<unsigned long long*>(&a);
    B = *reinterpret_cast<unsigned long long*>(&b);
    asm("mul.rn.f32x2 %0, %1, %2;" : "=l"(D) : "l"(A), "l"(B));
    return *reinterpret_cast<float2*>(&D);
}

// ---------------- fused kernel ----------------
// exp factorization:  exp(leaky(x1+x2)) = max(2^x1 * 2^x2, 2^(.2 x1) * 2^(.2 x2))
// (log2 domain; 2^x > 2^(0.2x) iff x > 0, which is exactly the leaky select)

#define E2_STRIDE 66   // floats per E2p/E2n row
#define R_STRIDE  36   // floats per r row (16B-aligned rows, broadcast-friendly)

struct Smem {
    union {
        struct {                           // live: phases 1..B
            float2 E1pk[WD * VV];          // 16384 B  [w][i] = (2^e1, 2^(.2 e1))
            float  E2p[VV * E2_STRIDE];    //  8448 B  [j][w] = 2^e2
            float  E2n[VV * E2_STRIDE];    //  8448 B  [j][w] = 2^(.2 e2)
        } e;
        struct {                           // live: phase 3
            float  hg[8 * TT * VV];        //  8192 B  per-warp h*g slice [warp][t][v]
        } p3;
    } u;                                   // 33280 B
    float  adjn[VV * VV];                  //  4096 B  [v][u] (persistent; computed inline)
    float  r[VV * R_STRIDE];               //  4608 B  [j][i] = 1/denominator (also prep scratch)
    float  asum[WD * VV];                  //  8192 B  [w][v] att_sum
    float4 Wt4[OO * 2];                    //   512 B  [o][half]: W[4h..4h+3][o]
    float  wa1[TT], wa2[TT];               //    64 B
};                                          // total 50,752 B -> 4 CTAs/SM

__global__ __launch_bounds__(256, 4)
void gat_main_kernel(const float* __restrict__ hin,
                     const float* __restrict__ W,
                     const float* __restrict__ a,
                     const float* __restrict__ Bp,
                     float* __restrict__ out) {
    extern __shared__ char smem_raw[];
    Smem& S = *reinterpret_cast<Smem*>(smem_raw);
    const int tid  = threadIdx.x;
    const int lane = tid & 31;
    const int warp = tid >> 5;
    const int n  = blockIdx.x >> 6;
    const int hh = blockIdx.x & 63;
    const float* __restrict__ hbase = hin + (size_t)(n * HH + hh) * (WD * TT * VV);

    // ---- inline prep: adjn (min-max norm + sym-degree norm), wa, Wt4 ----
    {
        float v[4]; float mn = 1e30f, mx = -1e30f;
        #pragma unroll
        for (int k = 0; k < 4; k++) {
            const int e = tid + k * 256;
            float x = Bp[e] + ((e >> 5) == (e & 31) ? 1.0f : 0.0f);
            v[k] = x;
            mn = fminf(mn, x); mx = fmaxf(mx, x);
        }
        #pragma unroll
        for (int o = 16; o; o >>= 1) {
            mn = fminf(mn, __shfl_xor_sync(0xFFFFFFFFu, mn, o));
            mx = fmaxf(mx, __shfl_xor_sync(0xFFFFFFFFu, mx, o));
        }
        if (lane == 0) { S.r[warp] = mn; S.r[8 + warp] = mx; }
        __syncthreads();
        if (tid == 0) {
            float m1 = S.r[0], m2 = S.r[8];
            #pragma unroll
            for (int q = 1; q < 8; q++) {
                m1 = fminf(m1, S.r[q]); m2 = fmaxf(m2, S.r[8 + q]);
            }
            S.r[16] = m1; S.r[17] = m2;
        }
        // stage Wt4 and wa in parallel with the final reduce
        if (tid < 32) {
            const int o = tid >> 1, hf = tid & 1;
            S.Wt4[o * 2 + hf] = make_float4(W[(4 * hf + 0) * OO + o],
                                            W[(4 * hf + 1) * OO + o],
                                            W[(4 * hf + 2) * OO + o],
                                            W[(4 * hf + 3) * OO + o]);
        }
        if (tid >= 32 && tid < 40) {
            const int t = tid - 32;
            float w1 = 0.f, w2 = 0.f;
            #pragma unroll
            for (int o = 0; o < OO; o++) {
                float wv = W[t * OO + o];
                w1 += wv * a[o];
                w2 += wv * a[OO + o];
            }
            S.wa1[t] = w1 * LOG2E;
            S.wa2[t] = w2 * LOG2E;
        }
        __syncthreads();
        const float gmn = S.r[16];
        const float inv = 1.0f / (S.r[17] - gmn);
        #pragma unroll
        for (int k = 0; k < 4; k++) {
            const int e = tid + k * 256;
            S.adjn[e] = (v[k] - gmn) * inv;
        }
        __syncthreads();
        if (tid < 32) {
            float s = 0.f;
            #pragma unroll
            for (int q = 0; q < 8; q++) {
                float4 t4 = *reinterpret_cast<const float4*>(&S.adjn[tid * VV + 4 * q]);
                s += t4.x + t4.y + t4.z + t4.w;
            }
            S.r[32 + tid] = rsqrtf(s);
        }
        __syncthreads();
        #pragma unroll
        for (int k = 0; k < 4; k++) {
            const int e = tid + k * 256;
            S.adjn[e] = S.adjn[e] * S.r[32 + (e >> 5)] * S.r[32 + (e & 31)];
        }
        __syncthreads();
    }

    // ---- phase 1: logits -> exponential tables, streaming h from gmem ----
    {
        float wa1r[TT], wa2r[TT];
        #pragma unroll
        for (int t = 0; t < TT; t++) { wa1r[t] = S.wa1[t]; wa2r[t] = S.wa2[t]; }
        #pragma unroll
        for (int s = 0; s < 2; s++) {
            const int slot = tid + s * 256;
            const int w  = slot >> 3;
            const int vq = slot & 7;
            float4 s1 = make_float4(0.f, 0.f, 0.f, 0.f);
            float4 s2 = make_float4(0.f, 0.f, 0.f, 0.f);
            #pragma unroll
            for (int t = 0; t < TT; t++) {
                float4 h4 = *reinterpret_cast<const float4*>(
                    &hbase[(w * TT + t) * VV + 4 * vq]);   // coalesced LDG.128
                s1.x = fmaf(h4.x, wa1r[t], s1.x);  s2.x = fmaf(h4.x, wa2r[t], s2.x);
                s1.y = fmaf(h4.y, wa1r[t], s1.y);  s2.y = fmaf(h4.y, wa2r[t], s2.y);
                s1.z = fmaf(h4.z, wa1r[t], s1.z);  s2.z = fmaf(h4.z, wa2r[t], s2.z);
                s1.w = fmaf(h4.w, wa1r[t], s1.w);  s2.w = fmaf(h4.w, wa2r[t], s2.w);
            }
            const float l1[4] = {s1.x, s1.y, s1.z, s1.w};
            const float l2[4] = {s2.x, s2.y, s2.z, s2.w};
            #pragma unroll
            for (int c = 0; c < 4; c++) {
                const int v = 4 * vq + c;
                S.u.e.E1pk[w * VV + v] = make_float2(ex2f(l1[c]), ex2f(ALPHA * l1[c]));
                S.u.e.E2p[v * E2_STRIDE + w] = ex2f(l2[c]);
                S.u.e.E2n[v * E2_STRIDE + w] = ex2f(ALPHA * l2[c]);
            }
        }
    }
    __syncthreads();

    // ---- pass A: r[j][i] = 1 / sum_w max(E1p*E2p, E1n*E2n) ----
    // warp -> 4 i rows, lane = j; E1 via 2 broadcast LDS.128; r stored transposed (STS.128).
    {
        const int i0 = warp * 4;
        const int j  = lane;
        float s0 = 0.f, s1 = 0.f, s2 = 0.f, s3 = 0.f;
        #pragma unroll 4
        for (int w = 0; w < WD; w++) {
            const float e2p = S.u.e.E2p[j * E2_STRIDE + w];
            const float e2n = S.u.e.E2n[j * E2_STRIDE + w];
            const float4 A = *reinterpret_cast<const float4*>(&S.u.e.E1pk[w * VV + i0]);
            const float4 B = *reinterpret_cast<const float4*>(&S.u.e.E1pk[w * VV + i0 + 2]);
            s0 += fmaxf(A.x * e2p, A.y * e2n);
            s1 += fmaxf(A.z * e2p, A.w * e2n);
            s2 += fmaxf(B.x * e2p, B.y * e2n);
            s3 += fmaxf(B.z * e2p, B.w * e2n);
        }
        *reinterpret_cast<float4*>(&S.r[j * R_STRIDE + i0]) =
            make_float4(rcpf(s0), rcpf(s1), rcpf(s2), rcpf(s3));
    }
    __syncthreads();

    // ---- pass B: asum[w][i] = sum_j max(E1p*E2p, E1n*E2n) * r[j][i] ----
    // warp -> 4 i rows, lane = w-pair; r via 1 broadcast LDS.128 per j.
    {
        const int i0 = warp * 4;
        const int w0 = 2 * lane;
        float2 E1p2[4], E1n2[4];
        #pragma unroll
        for (int k = 0; k < 4; k++) {
            float2 ea = S.u.e.E1pk[w0 * VV + i0 + k];
            float2 eb = S.u.e.E1pk[(w0 + 1) * VV + i0 + k];
            E1p2[k] = make_float2(ea.x, eb.x);
            E1n2[k] = make_float2(ea.y, eb.y);
        }
        float2 acc[4];
        #pragma unroll
        for (int k = 0; k < 4; k++) acc[k] = make_float2(0.f, 0.f);

        #pragma unroll 4
        for (int j = 0; j < VV; j++) {
            const float2 p2 = *reinterpret_cast<const float2*>(&S.u.e.E2p[j * E2_STRIDE + w0]);
            const float2 n2 = *reinterpret_cast<const float2*>(&S.u.e.E2n[j * E2_STRIDE + w0]);
            const float4 rr = *reinterpret_cast<const float4*>(&S.r[j * R_STRIDE + i0]);
            const float rk[4] = {rr.x, rr.y, rr.z, rr.w};
            #pragma unroll
            for (int k = 0; k < 4; k++) {
                float2 pp = fmul2(E1p2[k], p2);
                float2 pn = fmul2(E1n2[k], n2);
                acc[k].x = fmaf(fmaxf(pp.x, pn.x), rk[k], acc[k].x);
                acc[k].y = fmaf(fmaxf(pp.y, pn.y), rk[k], acc[k].y);
            }
        }
        #pragma unroll
        for (int k = 0; k < 4; k++) {
            S.asum[w0 * VV + i0 + k]       = acc[k].x;
            S.asum[(w0 + 1) * VV + i0 + k] = acc[k].y;
        }
    }
    __syncthreads();   // E-tables dead; union region becomes per-warp hg

    // ---- phase 3 (warp-autonomous): each warp owns w = warp*8 .. warp*8+7 ----
    {
        const int u = lane;
        float* hgw = S.u.p3.hg + warp * (TT * VV);
        const int sA = lane, sB = lane + 32;         // 64 float4 slots per w
        const int tA = sA >> 3, qA = sA & 7;
        const int tB = sB >> 3, qB = sB & 7;
        const int wbase = warp * 8;

        // prefetch first w
        float4 ha = *reinterpret_cast<const float4*>(&hbase[(wbase * TT + tA) * VV + 4 * qA]);
        float4 hb = *reinterpret_cast<const float4*>(&hbase[(wbase * TT + tB) * VV + 4 * qB]);

        #pragma unroll 1
        for (int c = 0; c < 8; c++) {
            const int w = wbase + c;
            // stage hg = h * asum for this w
            {
                const float4 a1 = *reinterpret_cast<const float4*>(&S.asum[w * VV + 4 * qA]);
                const float4 a2 = *reinterpret_cast<const float4*>(&S.asum[w * VV + 4 * qB]);
                float2 g1 = fmul2(make_float2(ha.x, ha.y), make_float2(a1.x, a1.y));
                float2 g2 = fmul2(make_float2(ha.z, ha.w), make_float2(a1.z, a1.w));
                *reinterpret_cast<float4*>(&hgw[tA * VV + 4 * qA]) =
                    make_float4(g1.x, g1.y, g2.x, g2.y);
                g1 = fmul2(make_float2(hb.x, hb.y), make_float2(a2.x, a2.y));
                g2 = fmul2(make_float2(hb.z, hb.w), make_float2(a2.z, a2.w));
                *reinterpret_cast<float4*>(&hgw[tB * VV + 4 * qB]) =
                    make_float4(g1.x, g1.y, g2.x, g2.y);
            }
            __syncwarp();
            // prefetch next w (latency hidden behind compute below)
            if (c < 7) {
                ha = *reinterpret_cast<const float4*>(&hbase[((w + 1) * TT + tA) * VV + 4 * qA]);
                hb = *reinterpret_cast<const float4*>(&hbase[((w + 1) * TT + tB) * VV + 4 * qB]);
            }

            // v-contraction: P[t][u] = sum_v hg[t][v] * adjn[v][u]
            float2 acc2[TT];
            #pragma unroll
            for (int t = 0; t < TT; t++) acc2[t] = make_float2(0.f, 0.f);
            #pragma unroll
            for (int vq = 0; vq < 8; vq++) {
                const float2 adjA = make_float2(S.adjn[(4 * vq + 0) * VV + u],
                                                S.adjn[(4 * vq + 1) * VV + u]);
                const float2 adjB = make_float2(S.adjn[(4 * vq + 2) * VV + u],
                                                S.adjn[(4 * vq + 3) * VV + u]);
                #pragma unroll
                for (int t = 0; t < TT; t++) {
                    float4 h4 = *reinterpret_cast<const float4*>(&hgw[t * VV + 4 * vq]); // broadcast
                    acc2[t] = ffma2(make_float2(h4.x, h4.y), adjA, acc2[t]);
                    acc2[t] = ffma2(make_float2(h4.z, h4.w), adjB, acc2[t]);
                }
            }
            float2 Pt2[4];
            #pragma unroll
            for (int tp = 0; tp < 4; tp++)
                Pt2[tp] = make_float2(acc2[2 * tp].x + acc2[2 * tp].y,
                                      acc2[2 * tp + 1].x + acc2[2 * tp + 1].y);

            // o-loop: out[o][u] = elu( sum_t W[t][o] * P[t][u] )
            float* outp = out + ((size_t)((n * WD + w) * HH + hh)) * (OO * VV) + u;
            #pragma unroll
            for (int o = 0; o < OO; o++) {
                const float4 Wa = S.Wt4[2 * o];       // broadcast LDS.128
                const float4 Wb = S.Wt4[2 * o + 1];
                float2 s2 = make_float2(0.f, 0.f);
                s2 = ffma2(Pt2[0], make_float2(Wa.x, Wa.y), s2);
                s2 = ffma2(Pt2[1], make_float2(Wa.z, Wa.w), s2);
                s2 = ffma2(Pt2[2], make_float2(Wb.x, Wb.y), s2);
                s2 = ffma2(Pt2[3], make_float2(Wb.z, Wb.w), s2);
                const float s = s2.x + s2.y;
                float r;
                if (s >= 0.0f) {
                    r = s;
                } else if (s > -0.0625f) {
                    r = s * fmaf(s, fmaf(s, 0.166666667f, 0.5f), 1.0f);
                } else {
                    r = ex2f(s * LOG2E) - 1.0f;
                }
                outp[o * VV] = r;
            }
            __syncwarp();   // protect hgw before next iteration's stores
        }
    }
}

// ---------------- launch ----------------
extern "C" void kernel_launch(void* const* d_in, const int* in_sizes, int n_in,
                              void* d_out, int out_size) {
    const float *h = nullptr, *W = nullptr, *a = nullptr, *Bp = nullptr;
    for (int i = 0; i < n_in; i++) {
        switch (in_sizes[i]) {
            case NN * HH * WD * TT * VV: h  = (const float*)d_in[i]; break; // 8388608
            case TT * OO:                W  = (const float*)d_in[i]; break; // 128
            case 2 * OO:                 a  = (const float*)d_in[i]; break; // 32
            case VV * VV:                Bp = (const float*)d_in[i]; break; // 1024
            default: break;
        }
    }
    float* out = (float*)d_out;

    cudaFuncSetAttribute(gat_main_kernel,
                         cudaFuncAttributeMaxDynamicSharedMemorySize,
                         (int)sizeof(Smem));

    gat_main_kernel<<<NN * HH, 256, sizeof(Smem)>>>(h, W, a, Bp, out);
}